// round 11
// baseline (speedup 1.0000x reference)
#include <cuda_runtime.h>
#include <math.h>

// Problem constants
#define NB    64
#define NH    512
#define NW    512
#define NPTS  200

#define EPS_LO 0.4999f
#define EPS_HI 0.5001f
#define ROWCAP 8          // borderline values stored per row (true count kept separately)
#define BPB    64         // kA blocks per batch

// bare MUFU.EX2 (no library fix-up code)
__device__ __forceinline__ float ex2_approx(float x) {
    float y;
    asm("ex2.approx.f32 %0, %1;" : "=f"(y) : "f"(x));
    return y;
}

// ---------------- scratch (device globals) ----------------
// All data slots are unconditionally rewritten every call. g_arrive is a
// monotone ticket counter: each call adds exactly BPB per batch, so
// (ticket & 63) == 63 selects the last arriving block of this call's batch
// on every graph replay (deterministic, no reset needed).
__device__ float    g_pmn[NB][BPB];
__device__ float    g_pmx[NB][BPB];
__device__ float    g_cnt[2][NB][NH];       // half 0: cols [0,256); half 1: cols [256,512)
__device__ int      g_blcnt[NB][NH];        // true borderline count per row
__device__ float    g_blv[NB][NH][ROWCAP];  // packed: +v -> half 0, -v -> half 1
__device__ unsigned g_arrive[NB];
__device__ float2   g_rt[2 * NB][NH];       // (tt, r) per unit (b*2+c)

// ---------------- prelude: runs in the LAST kA block of each batch --------
// 256 threads. Min/max reduce + exact correction + bounds + polar transform
// for both contour units of batch b; writes g_rt.
__device__ __noinline__ void batch_prelude(int b, const float4* __restrict__ in) {
    const float TWO_PI = 6.283185307179586f;
    __shared__ float p_x1[NH];
    __shared__ float p_red[16];
    __shared__ int   p_ovf;
    int tid = threadIdx.x;

    if (tid == 0) p_ovf = 0;
    __syncthreads();

    // reduce 64 min partials (threads 0..63) and 64 max partials (64..127)
    if (tid < BPB) {
        float v = g_pmn[b][tid];
#pragma unroll
        for (int o = 16; o; o >>= 1) v = fminf(v, __shfl_xor_sync(0xffffffffu, v, o));
        if ((tid & 31) == 0) p_red[tid >> 5] = v;               // slots 0,1
    } else if (tid < 2 * BPB) {
        float v = g_pmx[b][tid - BPB];
#pragma unroll
        for (int o = 16; o; o >>= 1) v = fmaxf(v, __shfl_xor_sync(0xffffffffu, v, o));
        if ((tid & 31) == 0) p_red[2 + ((tid - BPB) >> 5)] = v; // slots 2,3
    }
    int bl0 = g_blcnt[b][tid];
    int bl1 = g_blcnt[b][tid + 256];
    if (bl0 > ROWCAP || bl1 > ROWCAP) p_ovf = 1;  // benign race: any writer sets 1
    __syncthreads();

    float mn = fminf(p_red[0], p_red[1]);
    float mx = fmaxf(p_red[2], p_red[3]);
    float h  = 0.5f * (mx - mn);        // exact predicate: (v - mn) > h
    // Window validity: all v <= EPS_LO must fail, all v > EPS_HI must pass.
    bool ok = ((EPS_LO - mn) <= h) && ((EPS_HI - mn) > h) && (p_ovf == 0);

    for (int c = 0; c < 2; c++) {
        if (ok) {
            // exact correction; each thread owns rows tid and tid+256
#pragma unroll
            for (int k = 0; k < 2; k++) {
                int row = tid + k * 256;
                int blc = k ? bl1 : bl0;
                float x1 = g_cnt[c][b][row];
                float corr = 0.f;
                for (int j = 0; j < blc; j++) {
                    float pv = g_blv[b][row][j];
                    int   half = pv < 0.0f;
                    float v = fabsf(pv);
                    if (half == c && !((v - mn) > h)) corr += 1.0f;
                }
                p_x1[row] = x1 - corr;
            }
        } else {
            // never-expected exact fallback: full recount of this (b, c) half
            int w = tid >> 5, lane = tid & 31;
            for (int row = w; row < NH; row += 8) {
                const float4* p = in + ((size_t)(b * NH + row)) * 256 + c * 128;
                unsigned cnt = 0;
#pragma unroll
                for (int kk = 0; kk < 4; kk++) {
                    float4 v = p[lane + kk * 32];
                    cnt += (unsigned)((v.y - mn) > h) + (unsigned)((v.w - mn) > h);
                }
                cnt = __reduce_add_sync(0xffffffffu, cnt);
                if (lane == 0) p_x1[row] = (float)cnt;
            }
        }
        __syncthreads();

        // bounds: ythtop = 256 - sum(xa[0:256]), ythbottom = 256 + sum(xa[256:512])
        float st = fminf(p_x1[tid], 1.0f);
        float sb = fminf(p_x1[tid + 256], 1.0f);
#pragma unroll
        for (int o = 16; o; o >>= 1) {
            st += __shfl_xor_sync(0xffffffffu, st, o);
            sb += __shfl_xor_sync(0xffffffffu, sb, o);
        }
        if ((tid & 31) == 0) { p_red[tid >> 5] = st; p_red[8 + (tid >> 5)] = sb; }
        __syncthreads();
        float top = 256.0f, bot = 256.0f;
#pragma unroll
        for (int i = 0; i < 8; i++) { top -= p_red[i]; bot += p_red[8 + i]; }

        // polar transform (fix_radians -> [0, 2pi))
#pragma unroll
        for (int k = 0; k < 2; k++) {
            int row = tid + k * 256;
            float x1 = p_x1[row];
            float y1 = fminf(fmaxf((float)row, top), bot);
            float yc = y1 - 256.0f;
            float xc = -x1;
            float r  = sqrtf(xc * xc + yc * yc);
            float tt = atan2f(yc, xc);
            if (tt < 0.0f) tt += TWO_PI;
            g_rt[b * 2 + c][row] = make_float2(tt, r);
        }
        __syncthreads();   // p_x1 / p_red reused for next c
    }
}

// ---------------- KA: fused single pass + in-kernel prelude --------------
// One warp per row, 8 warps/block, 64 blocks/batch, grid 4096.
__global__ void __launch_bounds__(256, 8)
kA_pass(const float4* __restrict__ in) {
    int gwarp = (blockIdx.x * blockDim.x + threadIdx.x) >> 5;  // 0..32767
    int lane  = threadIdx.x & 31;
    int b   = gwarp >> 9;
    int row = gwarp & 511;

    const float4* p = in + ((size_t)(b * NH + row)) * 256;  // 256 float4/row

    // front-batched loads: 8 independent LDG.128 in flight
    float a[16];
#pragma unroll
    for (int i = 0; i < 8; i++) {
        float4 t = p[lane + i * 32];
        a[2 * i]     = t.y;            // channel-1 of pixel 2k
        a[2 * i + 1] = t.w;            // channel-1 of pixel 2k+1
    }

    float mn = 1e30f, mx = -1e30f;
    float md = 1e30f;                  // min |v - 0.5| (exact: Sterbenz near 0.5)
    unsigned cL = 0, cR = 0;
#pragma unroll
    for (int i = 0; i < 16; i++) {
        float v = a[i];
        mn = fminf(mn, v);
        mx = fmaxf(mx, v);
        md = fminf(md, fabsf(v - 0.5f));
        unsigned pred = (unsigned)(v > EPS_LO);
        if (i < 8) cL += pred; else cR += pred;   // idx <8 -> cols [0,256)
    }

    // borderline capture, guarded: window (0.4999,0.5001] implies
    // |v-0.5| <= 1.0002e-4 < 1.1e-4, so the guard is a strict superset.
    if (__ballot_sync(0xffffffffu, md <= 1.1e-4f)) {
        int base = 0;
#pragma unroll
        for (int i = 0; i < 16; i++) {
            float v = a[i];
            bool bl = (v > EPS_LO) && (v <= EPS_HI);
            unsigned mask = __ballot_sync(0xffffffffu, bl);
            if (bl) {
                int idx = base + __popc(mask & ((1u << lane) - 1u));
                if (idx < ROWCAP)
                    g_blv[b][row][idx] = (i < 8) ? v : -v;   // sign encodes half
            }
            base += __popc(mask);
        }
        if (lane == 0) g_blcnt[b][row] = base;
    } else {
        if (lane == 0) g_blcnt[b][row] = 0;
    }

    cL = __reduce_add_sync(0xffffffffu, cL);
    cR = __reduce_add_sync(0xffffffffu, cR);
    if (lane == 0) {
        g_cnt[0][b][row] = (float)cL;
        g_cnt[1][b][row] = (float)cR;
    }

    // block-level min/max partials (no atomics)
#pragma unroll
    for (int o = 16; o; o >>= 1) {
        mn = fminf(mn, __shfl_xor_sync(0xffffffffu, mn, o));
        mx = fmaxf(mx, __shfl_xor_sync(0xffffffffu, mx, o));
    }
    __shared__ float smn[8], smx[8];
    __shared__ unsigned s_ticket;
    int w = threadIdx.x >> 5;
    if (lane == 0) { smn[w] = mn; smx[w] = mx; }
    __syncthreads();
    if (threadIdx.x == 0) {
#pragma unroll
        for (int i = 1; i < 8; i++) { mn = fminf(mn, smn[i]); mx = fmaxf(mx, smx[i]); }
        g_pmn[b][blockIdx.x & 63] = mn;
        g_pmx[b][blockIdx.x & 63] = mx;
        __threadfence();               // cumulative: publishes whole block's writes
        s_ticket = atomicAdd(&g_arrive[b], 1u);
    }
    __syncthreads();

    // last arriving block of this batch runs the prelude (overlapped with
    // other batches' streaming blocks)
    if ((s_ticket & 63u) == 63u) {
        __threadfence();               // acquire side
        batch_prelude(b, in);
    }
}

// ---------------- K3b: Gaussian resampling ----------------
// grid 512 (= unit*4 + quarter), block 256. Each block: 64 point-slots,
// 4 partial sums each (sub = tid>>6, warp-uniform -> SMEM broadcasts).
// Range proof: xc <= 0 -> tt in [pi/2, 3pi/2]; ttn in [pi/2, 3pi/2) ->
//   d in (-pi, pi]: no wrap needed; +-2pi period candidates give ~0.
// Clamp dropped: reference clamps d^2>1 to exp(-100) ~ 3.7e-44 ~ 0.
// Weight: exp(-100 d^2) = ex2(-(S*tt - S*ttn)^2), S = sqrt(100*log2(e)).
__global__ void __launch_bounds__(256)
k3b_gauss(float* __restrict__ out) {
#if __CUDA_ARCH__ >= 900
    cudaGridDependencySynchronize();   // PDL: wait for kA's g_rt writes
#endif
    const float TT0 = (float)(M_PI / 2.0);
    const float DT  = (float)(M_PI / 200.0);
    const float SQK = 12.011224469026914f;  // sqrt(100 * log2(e))

    int unit = blockIdx.x >> 2;
    int q    = blockIdx.x & 3;
    int b = unit >> 1, c = unit & 1;
    int tid = threadIdx.x;

    __shared__ float4 s_rt4[NH / 2];   // 512 x (tt,r) as 256 float4
    __shared__ float  s_num[4][64];
    __shared__ float  s_den[4][64];

    s_rt4[tid] = ((const float4*)g_rt[unit])[tid];
    __syncthreads();

    int np  = tid & 63;                // point-slot within this quarter
    int sub = tid >> 6;                // 0..3, warp-uniform
    int n   = q * 64 + np;             // global point-slot (real < 200)
    float ttnS = (TT0 + (float)n * DT) * SQK;
    float num = 0.f, den = 0.f;
    int base4 = sub << 6;              // 64 float4 per sub-range (128 rows)
#pragma unroll 8
    for (int m = 0; m < 64; m++) {
        float4 v = s_rt4[base4 + m];
        float t0 = fmaf(v.x, SQK, -ttnS);
        float w0 = ex2_approx(-t0 * t0);
        den += w0;
        num = fmaf(w0, v.y, num);
        float t1 = fmaf(v.z, SQK, -ttnS);
        float w1 = ex2_approx(-t1 * t1);
        den += w1;
        num = fmaf(w1, v.w, num);
    }
    s_num[sub][np] = num;
    s_den[sub][np] = den;
    __syncthreads();

    if (tid < 64) {
        int nn = q * 64 + tid;
        if (nn < NPTS) {
            float nm = s_num[0][tid] + s_num[1][tid] + s_num[2][tid] + s_num[3][tid];
            float dn = s_den[0][tid] + s_den[1][tid] + s_den[2][tid] + s_den[3][tid];
            float ttn0 = TT0 + (float)nn * DT;
            float rn = nm / dn;
            float x = fmaf(rn, cosf(ttn0), 256.0f);
            float y = fmaf(rn, sinf(ttn0), 256.0f);
            int idx; float xo;
            if (c == 0) { idx = nn;       xo = x; }
            else        { idx = 399 - nn; xo = 512.0f - x; }
            out[((size_t)b * 400 + idx) * 2 + 0] = xo;
            out[((size_t)b * 400 + idx) * 2 + 1] = y;
        }
    }
}

extern "C" void kernel_launch(void* const* d_in, const int* in_sizes, int n_in,
                              void* d_out, int out_size) {
    const float4* in = (const float4*)d_in[0];
    float* out = (float*)d_out;

    kA_pass<<<4096, 256>>>(in);

    // k3b with PDL: launch setup overlaps kA's tail; device-side
    // cudaGridDependencySynchronize() enforces the data dependency.
    cudaLaunchConfig_t cfg = {};
    cfg.gridDim  = dim3(512);
    cfg.blockDim = dim3(256);
    cudaLaunchAttribute attr[1];
    attr[0].id = cudaLaunchAttributeProgrammaticStreamSerialization;
    attr[0].val.programmaticStreamSerializationAllowed = 1;
    cfg.attrs = attr;
    cfg.numAttrs = 1;
    cudaLaunchKernelEx(&cfg, k3b_gauss, out);
}

// round 12
// speedup vs baseline: 1.0934x; 1.0934x over previous
#include <cuda_runtime.h>
#include <math.h>

// Problem constants
#define NB    64
#define NH    512
#define NW    512
#define NPTS  200

#define EPS_LO 0.4999f
#define EPS_HI 0.5001f
#define ROWCAP 8          // borderline values stored per row (true count kept separately)
#define BPB    64         // kA blocks per batch

// bare MUFU.EX2 (no library fix-up code)
__device__ __forceinline__ float ex2_approx(float x) {
    float y;
    asm("ex2.approx.f32 %0, %1;" : "=f"(y) : "f"(x));
    return y;
}

// ---------------- scratch (device globals; every slot written every call,
// so no init kernel and no resets are needed) ----------------
__device__ float  g_pmn[NB][BPB];
__device__ float  g_pmx[NB][BPB];
// g_cnt[half][batch][row]: half 0 = cols [0,256), half 1 = cols [256,512)
__device__ float  g_cnt[2][NB][NH];
__device__ int    g_blcnt[NB][NH];          // true borderline count per row
__device__ float  g_blv[NB][NH][ROWCAP];    // packed: +v -> half 0, -v -> half 1
__device__ float2 g_rt[2 * NB][NH];         // (tt, r) per unit (b*2+c)

// ---------------- KA: fused single pass (DRAM-bound, atomic-free) --------
// One warp per row, 8 warps/block, 64 blocks/batch, grid 4096.
// Streaming loads (__ldcv) — data is read once, don't churn L2.
__global__ void __launch_bounds__(256, 8)
kA_pass(const float4* __restrict__ in) {
    int gwarp = (blockIdx.x * blockDim.x + threadIdx.x) >> 5;  // 0..32767
    int lane  = threadIdx.x & 31;
    int b   = gwarp >> 9;
    int row = gwarp & 511;

    const float4* p = in + ((size_t)(b * NH + row)) * 256;  // 256 float4/row

    // front-batched streaming loads: 8 independent LDG.128.CV in flight
    float a[16];
#pragma unroll
    for (int i = 0; i < 8; i++) {
        float4 t = __ldcv(p + lane + i * 32);
        a[2 * i]     = t.y;            // channel-1 of pixel 2k
        a[2 * i + 1] = t.w;            // channel-1 of pixel 2k+1
    }

    float mn = 1e30f, mx = -1e30f;
    float md = 1e30f;                  // min |v - 0.5|
    unsigned cL = 0, cR = 0;
#pragma unroll
    for (int i = 0; i < 16; i++) {
        float v = a[i];
        mn = fminf(mn, v);
        mx = fmaxf(mx, v);
        md = fminf(md, fabsf(v - 0.5f));
        unsigned pred = (unsigned)(v > EPS_LO);
        if (i < 8) cL += pred; else cR += pred;   // idx <8 -> cols [0,256)
    }

    // borderline capture, guarded: window (0.4999,0.5001] implies
    // |v-0.5| <= 1.0002e-4 < 1.1e-4, so the guard is a strict superset.
    if (__ballot_sync(0xffffffffu, md <= 1.1e-4f)) {
        int base = 0;
#pragma unroll
        for (int i = 0; i < 16; i++) {
            float v = a[i];
            bool bl = (v > EPS_LO) && (v <= EPS_HI);
            unsigned mask = __ballot_sync(0xffffffffu, bl);
            if (bl) {
                int idx = base + __popc(mask & ((1u << lane) - 1u));
                if (idx < ROWCAP)
                    g_blv[b][row][idx] = (i < 8) ? v : -v;   // sign encodes half
            }
            base += __popc(mask);
        }
        if (lane == 0) g_blcnt[b][row] = base;
    } else {
        if (lane == 0) g_blcnt[b][row] = 0;
    }

    cL = __reduce_add_sync(0xffffffffu, cL);
    cR = __reduce_add_sync(0xffffffffu, cR);
    if (lane == 0) {
        g_cnt[0][b][row] = (float)cL;
        g_cnt[1][b][row] = (float)cR;
    }

    // block-level min/max partials (no atomics)
#pragma unroll
    for (int o = 16; o; o >>= 1) {
        mn = fminf(mn, __shfl_xor_sync(0xffffffffu, mn, o));
        mx = fmaxf(mx, __shfl_xor_sync(0xffffffffu, mx, o));
    }
    __shared__ float smn[8], smx[8];
    int w = threadIdx.x >> 5;
    if (lane == 0) { smn[w] = mn; smx[w] = mx; }
    __syncthreads();
    if (threadIdx.x == 0) {
#pragma unroll
        for (int i = 1; i < 8; i++) { mn = fminf(mn, smn[i]); mx = fmaxf(mx, smx[i]); }
        g_pmn[b][blockIdx.x & 63] = mn;
        g_pmx[b][blockIdx.x & 63] = mx;
    }
}

// ---------------- K3a: prelude per (batch, contour) unit ----------------
// grid 128, block 512. minmax reduce + exact correction + bounds + polar
// transform; writes (tt, r) to g_rt[unit].
__global__ void k3a_prelude(const float4* __restrict__ in) {
    const float TWO_PI = 6.283185307179586f;

    int unit = blockIdx.x;
    int b = unit >> 1, c = unit & 1;
    int tid = threadIdx.x;             // == row

    __shared__ float s_x1[NH];
    __shared__ float s_red[16];
    __shared__ float s_bounds[2];
    __shared__ float s_mm[2];
    __shared__ int   s_ovf;

    if (tid == 0) s_ovf = 0;
    if (tid < BPB) {
        float v = g_pmn[b][tid];
#pragma unroll
        for (int o = 16; o; o >>= 1) v = fminf(v, __shfl_xor_sync(0xffffffffu, v, o));
        if ((tid & 31) == 0) s_red[tid >> 5] = v;
    } else if (tid < 2 * BPB) {
        float v = g_pmx[b][tid - BPB];
#pragma unroll
        for (int o = 16; o; o >>= 1) v = fmaxf(v, __shfl_xor_sync(0xffffffffu, v, o));
        if ((tid & 31) == 0) s_red[8 + ((tid - BPB) >> 5)] = v;
    }
    s_x1[tid] = g_cnt[c][b][tid];
    int blcnt = g_blcnt[b][tid];
    if (blcnt > ROWCAP) s_ovf = 1;     // benign race: any writer sets 1
    __syncthreads();
    if (tid == 0) {
        s_mm[0] = fminf(s_red[0], s_red[1]);
        s_mm[1] = fmaxf(s_red[8], s_red[9]);
    }
    __syncthreads();
    float mn = s_mm[0], mx = s_mm[1];
    float h  = 0.5f * (mx - mn);       // exact predicate: (v - mn) > h

    // Window validity: all v <= EPS_LO must fail, all v > EPS_HI must pass.
    bool ok = ((EPS_LO - mn) <= h) && ((EPS_HI - mn) > h) && (s_ovf == 0);
    if (ok) {
        float corr = 0.f;
        for (int j = 0; j < blcnt; j++) {
            float pv = g_blv[b][tid][j];
            int   half = pv < 0.0f;
            float v = fabsf(pv);
            if (half == c && !((v - mn) > h)) corr += 1.0f;
        }
        s_x1[tid] -= corr;
    } else {
        // never-expected exact fallback: full recount of this (b, c) half
        __syncthreads();
        int w = tid >> 5, lane = tid & 31;
        for (int row = w; row < NH; row += 16) {
            const float4* p = in + ((size_t)(b * NH + row)) * 256 + c * 128;
            unsigned cnt = 0;
#pragma unroll
            for (int k = 0; k < 4; k++) {
                float4 v = p[lane + k * 32];
                cnt += (unsigned)((v.y - mn) > h) + (unsigned)((v.w - mn) > h);
            }
            cnt = __reduce_add_sync(0xffffffffu, cnt);
            if (lane == 0) s_x1[row] = (float)cnt;
        }
    }
    __syncthreads();

    // bounds: ythtop = 256 - sum(xa[0:256]), ythbottom = 256 + sum(xa[256:512])
    {
        float s = fminf(s_x1[tid], 1.0f);
#pragma unroll
        for (int o = 16; o; o >>= 1) s += __shfl_xor_sync(0xffffffffu, s, o);
        if ((tid & 31) == 0) s_red[tid >> 5] = s;
    }
    __syncthreads();
    if (tid == 0) {
        float st = 0.f, sb = 0.f;
#pragma unroll
        for (int i = 0; i < 8; i++)  st += s_red[i];
#pragma unroll
        for (int i = 8; i < 16; i++) sb += s_red[i];
        s_bounds[0] = 256.0f - st;
        s_bounds[1] = 256.0f + sb;
    }
    __syncthreads();

    float x1 = s_x1[tid];
    float y1 = fminf(fmaxf((float)tid, s_bounds[0]), s_bounds[1]);
    float yc = y1 - 256.0f;
    float xc = -x1;
    float r  = sqrtf(xc * xc + yc * yc);
    float tt = atan2f(yc, xc);
    if (tt < 0.0f) tt += TWO_PI;       // fix_radians -> [0, 2pi)
    g_rt[unit][tid] = make_float2(tt, r);
}

// ---------------- K3b: Gaussian resampling ----------------
// grid 512 (= unit*4 + quarter), block 256. Each block: 64 point-slots,
// 4 partial sums each (sub = tid>>6, warp-uniform -> SMEM broadcasts).
// Range proof: xc <= 0 -> tt in [pi/2, 3pi/2]; ttn in [pi/2, 3pi/2) ->
//   d in (-pi, pi]: no wrap needed; +-2pi period candidates give ~0.
// Clamp dropped: reference clamps d^2>1 to exp(-100) ~ 3.7e-44 ~ 0.
// Weight: exp(-100 d^2) = ex2(-(S*tt - S*ttn)^2), S = sqrt(100*log2(e)).
__global__ void __launch_bounds__(256)
k3b_gauss(float* __restrict__ out) {
    const float TT0 = (float)(M_PI / 2.0);
    const float DT  = (float)(M_PI / 200.0);
    const float SQK = 12.011224469026914f;  // sqrt(100 * log2(e))

    int unit = blockIdx.x >> 2;
    int q    = blockIdx.x & 3;
    int b = unit >> 1, c = unit & 1;
    int tid = threadIdx.x;

    __shared__ float4 s_rt4[NH / 2];   // 512 x (tt,r) as 256 float4
    __shared__ float  s_num[4][64];
    __shared__ float  s_den[4][64];

    s_rt4[tid] = ((const float4*)g_rt[unit])[tid];
    __syncthreads();

    int np  = tid & 63;                // point-slot within this quarter
    int sub = tid >> 6;                // 0..3, warp-uniform
    int n   = q * 64 + np;             // global point-slot (real < 200)
    float ttnS = (TT0 + (float)n * DT) * SQK;
    float num = 0.f, den = 0.f;
    int base4 = sub << 6;              // 64 float4 per sub-range (128 rows)
#pragma unroll 8
    for (int m = 0; m < 64; m++) {
        float4 v = s_rt4[base4 + m];
        float t0 = fmaf(v.x, SQK, -ttnS);
        float w0 = ex2_approx(-t0 * t0);
        den += w0;
        num = fmaf(w0, v.y, num);
        float t1 = fmaf(v.z, SQK, -ttnS);
        float w1 = ex2_approx(-t1 * t1);
        den += w1;
        num = fmaf(w1, v.w, num);
    }
    s_num[sub][np] = num;
    s_den[sub][np] = den;
    __syncthreads();

    if (tid < 64) {
        int nn = q * 64 + tid;
        if (nn < NPTS) {
            float nm = s_num[0][tid] + s_num[1][tid] + s_num[2][tid] + s_num[3][tid];
            float dn = s_den[0][tid] + s_den[1][tid] + s_den[2][tid] + s_den[3][tid];
            float ttn0 = TT0 + (float)nn * DT;
            float rn = nm / dn;
            float x = fmaf(rn, cosf(ttn0), 256.0f);
            float y = fmaf(rn, sinf(ttn0), 256.0f);
            int idx; float xo;
            if (c == 0) { idx = nn;       xo = x; }
            else        { idx = 399 - nn; xo = 512.0f - x; }
            out[((size_t)b * 400 + idx) * 2 + 0] = xo;
            out[((size_t)b * 400 + idx) * 2 + 1] = y;
        }
    }
}

extern "C" void kernel_launch(void* const* d_in, const int* in_sizes, int n_in,
                              void* d_out, int out_size) {
    const float4* in = (const float4*)d_in[0];
    float* out = (float*)d_out;

    kA_pass<<<4096, 256>>>(in);
    k3a_prelude<<<128, 512>>>(in);
    k3b_gauss<<<512, 256>>>(out);
}